// round 15
// baseline (speedup 1.0000x reference)
#include <cuda_runtime.h>
#include <cuda_bf16.h>
#include <cstdint>

// Nearest-of-16-sorted-qpoints quantizer, round 12 (final combination).
// Floor established: ~77.5-78.6us kernel across all sane configs, DRAM ~78%.
// R12 merges the two best independent features:
//   - 256-bit global ld/st (R6: fewest LSU issues, 1 LDG.256+1 STG.256/thread)
//   - L1::no_allocate on both streams (R10/R11: current best sample)
// Quantizer: proven 4-level LDS binary search (rel_err == 0 all rounds).

__device__ __forceinline__ float quant1(float v, float m7,
                                        const float* __restrict__ s_mid,
                                        const float* __restrict__ s_qp)
{
    int i = (v > m7) ? 8 : 0;              // level 0: uniform register compare
    i += (v > s_mid[i + 3]) ? 4 : 0;       // level 1: LDS
    i += (v > s_mid[i + 1]) ? 2 : 0;       // level 2: LDS
    i += (v > s_mid[i]) ? 1 : 0;           // level 3: LDS
    return s_qp[i];                         // value LUT: LDS broadcast
}

__global__ __launch_bounds__(256, 7) void QPointQuantize_kernel(
    const float* __restrict__ x,
    const float* __restrict__ q,
    float* __restrict__ out,
    int n)
{
    __shared__ float s_qp[16];
    __shared__ float s_mid[16];   // 15 used; banks 0-14, conflict-free

    // One-stage init straight from global q (16 B, L2-resident after warp 0).
    if (threadIdx.x < 16) {
        float qi = q[threadIdx.x];
        s_qp[threadIdx.x] = qi;
        if (threadIdx.x < 15)
            s_mid[threadIdx.x] = 0.5f * (qi + q[threadIdx.x + 1]);
    }
    __syncthreads();

    const float m7 = s_mid[7];    // uniform -> register, skips one LDS level

    // 8 contiguous floats (32 bytes) per thread via one 256-bit access.
    long long base = (long long)(blockIdx.x * 256 + threadIdx.x) * 8;
    if (base + 8 > n) return;     // exact divide for this shape; safety only

    const float* xp = x + base;
    float*       op = out + base;

    float v0, v1, v2, v3, v4, v5, v6, v7;
    asm volatile(
        "ld.global.L1::no_allocate.v8.f32 {%0,%1,%2,%3,%4,%5,%6,%7}, [%8];"
        : "=f"(v0), "=f"(v1), "=f"(v2), "=f"(v3),
          "=f"(v4), "=f"(v5), "=f"(v6), "=f"(v7)
        : "l"(xp));

    float o0 = quant1(v0, m7, s_mid, s_qp);
    float o1 = quant1(v1, m7, s_mid, s_qp);
    float o2 = quant1(v2, m7, s_mid, s_qp);
    float o3 = quant1(v3, m7, s_mid, s_qp);
    float o4 = quant1(v4, m7, s_mid, s_qp);
    float o5 = quant1(v5, m7, s_mid, s_qp);
    float o6 = quant1(v6, m7, s_mid, s_qp);
    float o7 = quant1(v7, m7, s_mid, s_qp);

    asm volatile(
        "st.global.L1::no_allocate.v8.f32 [%0], {%1,%2,%3,%4,%5,%6,%7,%8};"
        :: "l"(op),
           "f"(o0), "f"(o1), "f"(o2), "f"(o3),
           "f"(o4), "f"(o5), "f"(o6), "f"(o7)
        : "memory");
}

extern "C" void kernel_launch(void* const* d_in, const int* in_sizes, int n_in,
                              void* d_out, int out_size)
{
    const float* x = (const float*)d_in[0];   // (64, 1024, 1024) fp32
    const float* q = (const float*)d_in[1];   // (16,) fp32 sorted
    float* out = (float*)d_out;

    int n = in_sizes[0];          // 67,108,864 (divisible by 8)

    int threads = 256;
    int elems_per_block = threads * 8;                    // 2048 elements
    int blocks = (n + elems_per_block - 1) / elems_per_block;  // 32,768

    QPointQuantize_kernel<<<blocks, threads>>>(x, q, out, n);
}